// round 4
// baseline (speedup 1.0000x reference)
#include <cuda_runtime.h>

#define BB    32
#define CINN  16
#define COUTT 32
#define HH    14
#define WW    14
#define KK    5
#define OHH   5
#define OWW   5
#define HWSZ  (HH*WW)        // 196
#define IMG   (HWSZ*HWSZ)    // 38416
#define IMG4  (IMG/4)        // 9604

// fused-cov tiling
#define IG        2                      // output channels per block
#define CS_PITCH  197                    // 196 cols + 1 pad (stride mod 32 = 5)
#define TS_W      169                    // 13x13 needed positions (mod 32 = 9)
#define SMEM_CS   (HWSZ * CS_PITCH)                  // 38612 floats
#define SMEM_TS   (IG * 25 * TS_W)                   //  8450 floats
#define SMEM_WS   (IG * 25)                          //    50 floats
#define SMEM_FLOATS (SMEM_CS + SMEM_TS + SMEM_WS)    // 47112 floats
#define SMEM_BYTES  (SMEM_FLOATS * 4)                // 188448 B < 227KB

// Scratch: channel-reduced covariance (L2-resident, 4.9 MB)
__device__ float g_Csum[BB * IMG];

// ---------------------------------------------------------------------------
// Kernel 1: Csum[b, hw2, hw4] = sum_c C[b,c,hw2,hw4]   (streams 78.7 MB HBM)
// ---------------------------------------------------------------------------
__global__ void reduce_c_kernel(const float4* __restrict__ C4) {
    int idx = blockIdx.x * blockDim.x + threadIdx.x;
    if (idx >= BB * IMG4) return;
    int b = idx / IMG4;
    int j = idx - b * IMG4;
    const float4* p = C4 + (size_t)b * CINN * IMG4 + j;
    float ax = 0.f, ay = 0.f, az = 0.f, aw = 0.f;
#pragma unroll
    for (int c = 0; c < CINN; c++) {
        float4 v = p[(size_t)c * IMG4];
        ax += v.x; ay += v.y; az += v.z; aw += v.w;
    }
    reinterpret_cast<float4*>(g_Csum)[idx] = make_float4(ax, ay, az, aw);
}

// ---------------------------------------------------------------------------
// Kernel 2 (fused cov): per block = (batch b, IG output channels).
//   Stage L: Csum[b] (196x196) -> smem with pitch 197
//   Stage A: T[g][p][j] = sum_k w[i,k] * Cs[j][win_p(k)]   (conv over dims 4,5)
//   Stage B: out[b,i,q,p] = sum_a w[i,a] * T[g][p][win_q(a)] (conv over dims 2,3)
// ---------------------------------------------------------------------------
__global__ void cov_fused_kernel(const float* __restrict__ w,
                                 float* __restrict__ out_cov) {
    extern __shared__ float sm[];
    float* Cs = sm;                       // [196][197]
    float* Ts = sm + SMEM_CS;             // [IG][25][169]
    float* ws = sm + SMEM_CS + SMEM_TS;   // [IG][25]

    const int tid  = threadIdx.x;
    const int lane = tid & 31;
    const int warp = tid >> 5;
    const int i0   = blockIdx.x * IG;     // first output channel
    const int b    = blockIdx.y;

    // -- load weights --
    for (int t = tid; t < IG * 25; t += blockDim.x)
        ws[t] = w[i0 * 25 + t];

    // -- Stage L: load Csum[b] (coalesced 128B rows, padded pitch) --
    const float* src = g_Csum + (size_t)b * IMG;
    for (int r = warp; r < HWSZ; r += 8) {
        const float* srow = src + r * HWSZ;
        float* drow = Cs + r * CS_PITCH;
        for (int c = lane; c < HWSZ; c += 32)
            drow[c] = srow[c];
    }
    __syncthreads();

    // -- Stage A: first conv (dims 4,5) for needed (h2,w2) in [0,13)^2 --
    for (int e = tid; e < IG * 25 * TS_W; e += blockDim.x) {
        int g   = e / (25 * TS_W);
        int rem = e - g * (25 * TS_W);
        int p   = rem / TS_W;             // y1*5+x1
        int j   = rem - p * TS_W;         // h2*13+w2
        int y1 = p / OWW, x1 = p - y1 * OWW;
        int h2 = j / 13,  w2 = j - h2 * 13;
        const float* base = Cs + (h2 * WW + w2) * CS_PITCH
                            + (2 * y1) * WW + 2 * x1;
        const float* wk = ws + g * 25;
        float acc = 0.f;
#pragma unroll
        for (int r = 0; r < KK; r++)
#pragma unroll
            for (int c = 0; c < KK; c++)
                acc += wk[r * KK + c] * base[r * WW + c];
        Ts[e] = acc;
    }
    __syncthreads();

    // -- Stage B: second conv (dims 2,3), write final cov --
    for (int o = tid; o < IG * 625; o += blockDim.x) {
        int g   = o / 625;
        int rem = o - g * 625;
        int q   = rem / 25;               // y2*5+x2
        int p   = rem - q * 25;           // y1*5+x1
        int y2 = q / OWW, x2 = q - y2 * OWW;
        const float* base = Ts + (g * 25 + p) * TS_W + (2 * y2) * 13 + 2 * x2;
        const float* wk = ws + g * 25;
        float acc = 0.f;
#pragma unroll
        for (int r = 0; r < KK; r++)
#pragma unroll
            for (int c = 0; c < KK; c++)
                acc += wk[r * KK + c] * base[r * 13 + c];
        out_cov[((size_t)(b * COUTT + i0 + g)) * 625 + rem] = acc;
    }
}

// ---------------------------------------------------------------------------
// Kernel 3: mean path via cin-reduction first.
//   usum[b] = sum_c u[b,c];  out_mean[b,i] = conv(usum[b], w[i])
// grid = B, block = 256
// ---------------------------------------------------------------------------
__global__ void mean_kernel(const float* __restrict__ u,
                            const float* __restrict__ w,
                            float* __restrict__ out) {
    __shared__ float usum[HWSZ];
    __shared__ float ws[COUTT * 25];
    int tid = threadIdx.x;
    int b   = blockIdx.x;

    for (int t = tid; t < HWSZ; t += blockDim.x) {
        const float* up = u + (size_t)b * CINN * HWSZ + t;
        float a = 0.f;
#pragma unroll
        for (int c = 0; c < CINN; c++) a += up[c * HWSZ];
        usum[t] = a;
    }
    for (int t = tid; t < COUTT * 25; t += blockDim.x) ws[t] = w[t];
    __syncthreads();

    for (int o = tid; o < COUTT * 25; o += blockDim.x) {
        int i   = o / 25;
        int rem = o - i * 25;
        int y = rem / OWW, x = rem - y * OWW;
        const float* base = usum + (2 * y) * WW + 2 * x;
        const float* wk = ws + i * 25;
        float acc = 0.f;
#pragma unroll
        for (int r = 0; r < KK; r++)
#pragma unroll
            for (int c = 0; c < KK; c++)
                acc += wk[r * KK + c] * base[r * WW + c];
        out[(size_t)b * COUTT * 25 + o] = acc;
    }
}

// ---------------------------------------------------------------------------
extern "C" void kernel_launch(void* const* d_in, const int* in_sizes, int n_in,
                              void* d_out, int out_size) {
    const float* u = (const float*)d_in[0];   // [32,16,14,14]
    const float* C = (const float*)d_in[1];   // [32,16,14,14,14,14]
    const float* w = (const float*)d_in[2];   // [32,1,5,5]
    float* out      = (float*)d_out;
    float* out_mean = out;                               // 25600 floats
    float* out_cov  = out + BB * COUTT * OHH * OWW;      // 640000 floats

    static bool attr_done = false;
    if (!attr_done) {
        cudaFuncSetAttribute(cov_fused_kernel,
                             cudaFuncAttributeMaxDynamicSharedMemorySize,
                             SMEM_BYTES);
        attr_done = true;
    }

    // 1) channel reduction of C (HBM-bound)
    reduce_c_kernel<<<(BB * IMG4 + 255) / 256, 256>>>((const float4*)C);

    // 2) fused double conv for covariance (L2-bound)
    dim3 gcov(COUTT / IG, BB);            // 16 x 32 = 512 blocks
    cov_fused_kernel<<<gcov, 256, SMEM_BYTES>>>(w, out_cov);

    // 3) mean path (tiny)
    mean_kernel<<<BB, 256>>>(u, w, out_mean);
}

// round 5
// speedup vs baseline: 4.4264x; 4.4264x over previous
#include <cuda_runtime.h>

#define BB    32
#define CINN  16
#define COUTT 32
#define HH    14
#define WW    14
#define KK    5
#define OHH   5
#define OWW   5
#define HWSZ  (HH*WW)        // 196
#define IMG   (HWSZ*HWSZ)    // 38416
#define IMG4  (IMG/4)        // 9604
#define TS_W  169            // only (h2,w2) in [0,13)^2 are ever used by conv2
#define NPAIR (COUTT/2)      // 16 channel pairs

// Scratch (global device arrays; no allocations)
__device__ float g_Csum[BB * IMG];                               // 4.9 MB
__device__ float g_T[(size_t)BB * COUTT * 25 * TS_W];            // 17.3 MB

// ---- packed f32x2 helpers (Blackwell FFMA2) --------------------------------
__device__ __forceinline__ unsigned long long pack2(float lo, float hi) {
    unsigned long long r;
    asm("mov.b64 %0, {%1, %2};" : "=l"(r) : "f"(lo), "f"(hi));
    return r;
}
__device__ __forceinline__ unsigned long long bcast2(float v) {
    unsigned long long r;
    asm("mov.b64 %0, {%1, %1};" : "=l"(r) : "f"(v));
    return r;
}
__device__ __forceinline__ void fma2(unsigned long long& d,
                                     unsigned long long a,
                                     unsigned long long b) {
    asm("fma.rn.f32x2 %0, %1, %2, %0;" : "+l"(d) : "l"(a), "l"(b));
}
__device__ __forceinline__ void unpack2(unsigned long long v, float& lo, float& hi) {
    asm("mov.b64 {%0, %1}, %2;" : "=f"(lo), "=f"(hi) : "l"(v));
}

// ---------------------------------------------------------------------------
// Kernel 1: Csum[b, hw2, hw4] = sum_c C[b,c,hw2,hw4]   (streams 78.7 MB HBM)
// ---------------------------------------------------------------------------
__global__ void reduce_c_kernel(const float4* __restrict__ C4) {
    int idx = blockIdx.x * blockDim.x + threadIdx.x;
    if (idx >= BB * IMG4) return;
    int b = idx / IMG4;
    int j = idx - b * IMG4;
    const float4* p = C4 + (size_t)b * CINN * IMG4 + j;
    float ax = 0.f, ay = 0.f, az = 0.f, aw = 0.f;
#pragma unroll
    for (int c = 0; c < CINN; c++) {
        float4 v = p[(size_t)c * IMG4];
        ax += v.x; ay += v.y; az += v.z; aw += v.w;
    }
    reinterpret_cast<float4*>(g_Csum)[idx] = make_float4(ax, ay, az, aw);
}

// ---------------------------------------------------------------------------
// Kernel 2: first conv (dims 4,5) for all 32 channels, only the 169 needed
// (h2,w2) positions.  FFMA2: channels processed in pairs.
// T[b][i][p][j] = sum_k w[i,k] * Csum[b, j_row, win_p(k)]
// grid = (25 p-positions, B), block = 192 (tid<169 = one (h2,w2) each)
// ---------------------------------------------------------------------------
__global__ void conv1_kernel(const float* __restrict__ w) {
    __shared__ unsigned long long ws2[25 * NPAIR];   // [k][ipair] packed weights
    int tid = threadIdx.x;

    for (int t = tid; t < 25 * NPAIR; t += blockDim.x) {
        int k  = t / NPAIR;
        int ip = t - k * NPAIR;
        ws2[t] = pack2(w[(2 * ip) * 25 + k], w[(2 * ip + 1) * 25 + k]);
    }
    __syncthreads();

    int yx = blockIdx.x;              // p = y1*5+x1
    int b  = blockIdx.y;
    int y1 = yx / OWW, x1 = yx - y1 * OWW;

    if (tid < TS_W) {
        int h2 = tid / 13, w2 = tid - h2 * 13;
        const float* src = g_Csum + (size_t)b * IMG + (h2 * WW + w2) * HWSZ
                           + (2 * y1) * WW + 2 * x1;
        unsigned long long patch2[25];
#pragma unroll
        for (int r = 0; r < KK; r++)
#pragma unroll
            for (int c = 0; c < KK; c++)
                patch2[r * KK + c] = bcast2(__ldg(src + r * WW + c));

        float* dst = g_T + (((size_t)b * COUTT) * 25 + yx) * TS_W + tid;
#pragma unroll
        for (int ip = 0; ip < NPAIR; ip++) {
            unsigned long long acc = 0ull;   // {+0.f, +0.f}
#pragma unroll
            for (int k = 0; k < 25; k++)
                fma2(acc, patch2[k], ws2[k * NPAIR + ip]);
            float lo, hi;
            unpack2(acc, lo, hi);
            dst[(size_t)(2 * ip)     * 25 * TS_W] = lo;   // coalesced over tid
            dst[(size_t)(2 * ip + 1) * 25 * TS_W] = hi;
        }
    }
}

// ---------------------------------------------------------------------------
// Kernel 3: second conv (dims 2,3).
// out_cov[b,i,q,p] = sum_a w[i,a] * T[b,i,p, win_q(a)]
// grid = B*COUT, block = 640 (tid<625 = one output each)
// ---------------------------------------------------------------------------
__global__ void conv2_kernel(const float* __restrict__ w,
                             float* __restrict__ out_cov) {
    __shared__ float Ts[25 * TS_W];   // 4225 floats = 16.9 KB
    __shared__ float ws[25];
    int tid = threadIdx.x;
    int bi  = blockIdx.x;             // b*32 + i
    int i   = bi % COUTT;

    const float* tsrc = g_T + (size_t)bi * 25 * TS_W;
    for (int k = tid; k < 25 * TS_W; k += blockDim.x) Ts[k] = tsrc[k];
    if (tid < 25) ws[tid] = w[i * 25 + tid];
    __syncthreads();

    if (tid < 625) {
        int q = tid / 25;             // y2*5+x2
        int p = tid - q * 25;         // y1*5+x1
        int y2 = q / OWW, x2 = q - y2 * OWW;
        const float* base = Ts + p * TS_W + (2 * y2) * 13 + 2 * x2;
        float acc = 0.f;
#pragma unroll
        for (int r = 0; r < KK; r++)
#pragma unroll
            for (int c = 0; c < KK; c++)
                acc += ws[r * KK + c] * base[r * 13 + c];
        out_cov[(size_t)bi * 625 + tid] = acc;   // coalesced
    }
}

// ---------------------------------------------------------------------------
// Kernel 4: mean path via cin-reduction first.
//   usum[b] = sum_c u[b,c];  out_mean[b,i] = conv(usum[b], w[i])
// ---------------------------------------------------------------------------
__global__ void mean_kernel(const float* __restrict__ u,
                            const float* __restrict__ w,
                            float* __restrict__ out) {
    __shared__ float usum[HWSZ];
    __shared__ float ws[COUTT * 25];
    int tid = threadIdx.x;
    int b   = blockIdx.x;

    for (int t = tid; t < HWSZ; t += blockDim.x) {
        const float* up = u + (size_t)b * CINN * HWSZ + t;
        float a = 0.f;
#pragma unroll
        for (int c = 0; c < CINN; c++) a += up[c * HWSZ];
        usum[t] = a;
    }
    for (int t = tid; t < COUTT * 25; t += blockDim.x) ws[t] = w[t];
    __syncthreads();

    for (int o = tid; o < COUTT * 25; o += blockDim.x) {
        int i   = o / 25;
        int rem = o - i * 25;
        int y = rem / OWW, x = rem - y * OWW;
        const float* base = usum + (2 * y) * WW + 2 * x;
        const float* wk = ws + i * 25;
        float acc = 0.f;
#pragma unroll
        for (int r = 0; r < KK; r++)
#pragma unroll
            for (int c = 0; c < KK; c++)
                acc += wk[r * KK + c] * base[r * WW + c];
        out[(size_t)b * COUTT * 25 + o] = acc;
    }
}

// ---------------------------------------------------------------------------
extern "C" void kernel_launch(void* const* d_in, const int* in_sizes, int n_in,
                              void* d_out, int out_size) {
    const float* u = (const float*)d_in[0];   // [32,16,14,14]
    const float* C = (const float*)d_in[1];   // [32,16,14,14,14,14]
    const float* w = (const float*)d_in[2];   // [32,1,5,5]
    float* out      = (float*)d_out;
    float* out_mean = out;                               // 25600 floats
    float* out_cov  = out + BB * COUTT * OHH * OWW;      // 640000 floats

    // 1) channel reduction of C (HBM-bound, ~17 us)
    reduce_c_kernel<<<(BB * IMG4 + 255) / 256, 256>>>((const float4*)C);

    // 2) first conv over dims (4,5), FFMA2, only 169 needed positions
    dim3 g1(OHH * OWW, BB);
    conv1_kernel<<<g1, 192>>>(w);

    // 3) second conv over dims (2,3)
    conv2_kernel<<<BB * COUTT, 640>>>(w, out_cov);

    // 4) mean path (independent, tiny)
    mean_kernel<<<BB, 256>>>(u, w, out_mean);
}

// round 6
// speedup vs baseline: 4.4846x; 1.0132x over previous
#include <cuda_runtime.h>

#define BB    32
#define CINN  16
#define COUTT 32
#define HH    14
#define WW    14
#define KK    5
#define OHH   5
#define OWW   5
#define HWSZ  (HH*WW)        // 196
#define IMG   (HWSZ*HWSZ)    // 38416
#define IMG4  (IMG/4)        // 9604
#define TS_W  169            // only (h2,w2) in [0,13)^2 are used by conv2
#define NPAIR (COUTT/2)      // 16 channel pairs

#define RED_BLOCKS   ((BB * IMG4 + 255) / 256)           // 1201
#define USUM_ELEMS   (BB * HWSZ)                          // 6272
#define USUM_BLOCKS  ((USUM_ELEMS + 255) / 256)           // 25

// Scratch (global device arrays; no allocations)
__device__ float g_Csum[BB * IMG];                        // 4.9 MB (L2-resident)
__device__ float g_T[(size_t)BB * COUTT * 25 * TS_W];     // 17.3 MB (L2-resident)
__device__ float g_usum[USUM_ELEMS];                      // 25 KB

// ---- packed f32x2 helpers (Blackwell FFMA2) --------------------------------
__device__ __forceinline__ unsigned long long pack2(float lo, float hi) {
    unsigned long long r;
    asm("mov.b64 %0, {%1, %2};" : "=l"(r) : "f"(lo), "f"(hi));
    return r;
}
__device__ __forceinline__ unsigned long long bcast2(float v) {
    unsigned long long r;
    asm("mov.b64 %0, {%1, %1};" : "=l"(r) : "f"(v));
    return r;
}
__device__ __forceinline__ void fma2(unsigned long long& d,
                                     unsigned long long a,
                                     unsigned long long b) {
    asm("fma.rn.f32x2 %0, %1, %2, %0;" : "+l"(d) : "l"(a), "l"(b));
}
__device__ __forceinline__ void unpack2(unsigned long long v, float& lo, float& hi) {
    asm("mov.b64 {%0, %1}, %2;" : "=f"(lo), "=f"(hi) : "l"(v));
}

// ---------------------------------------------------------------------------
// Kernel 1: blocks [0,1201):  Csum[b,hw2,hw4] = sum_c C[b,c,...]  (78.7 MB)
//           blocks [1201,1226): usum[b,hw]    = sum_c u[b,c,hw]   (0.4 MB)
// ---------------------------------------------------------------------------
__global__ void reduce_c_kernel(const float4* __restrict__ C4,
                                const float* __restrict__ u) {
    if (blockIdx.x < RED_BLOCKS) {
        int idx = blockIdx.x * blockDim.x + threadIdx.x;
        if (idx >= BB * IMG4) return;
        int b = idx / IMG4;
        int j = idx - b * IMG4;
        const float4* p = C4 + (size_t)b * CINN * IMG4 + j;
        float ax = 0.f, ay = 0.f, az = 0.f, aw = 0.f;
#pragma unroll
        for (int c = 0; c < CINN; c++) {
            float4 v = __ldcs(p + (size_t)c * IMG4);   // streaming: evict-first
            ax += v.x; ay += v.y; az += v.z; aw += v.w;
        }
        reinterpret_cast<float4*>(g_Csum)[idx] = make_float4(ax, ay, az, aw);
    } else {
        int t = (blockIdx.x - RED_BLOCKS) * blockDim.x + threadIdx.x;
        if (t >= USUM_ELEMS) return;
        int b  = t / HWSZ;
        int hw = t - b * HWSZ;
        const float* up = u + (size_t)b * CINN * HWSZ + hw;
        float a = 0.f;
#pragma unroll
        for (int c = 0; c < CINN; c++) a += up[c * HWSZ];
        g_usum[t] = a;
    }
}

// ---------------------------------------------------------------------------
// Kernel 2: first conv (dims 4,5), all 32 channels, only 169 needed (h2,w2).
// FFMA2: channels in pairs.  T[b][i][p][j] = sum_k w[i,k]*Csum[b,j,win_p(k)]
// grid = (25, B), block = 192 (tid<169 active)
// ---------------------------------------------------------------------------
__global__ void conv1_kernel(const float* __restrict__ w) {
    __shared__ unsigned long long ws2[25 * NPAIR];   // [k][ipair]
    int tid = threadIdx.x;

    for (int t = tid; t < 25 * NPAIR; t += blockDim.x) {
        int k  = t / NPAIR;
        int ip = t - k * NPAIR;
        ws2[t] = pack2(w[(2 * ip) * 25 + k], w[(2 * ip + 1) * 25 + k]);
    }
    __syncthreads();

    int yx = blockIdx.x;              // p = y1*5+x1
    int b  = blockIdx.y;
    int y1 = yx / OWW, x1 = yx - y1 * OWW;

    if (tid < TS_W) {
        int h2 = tid / 13, w2 = tid - h2 * 13;
        const float* src = g_Csum + (size_t)b * IMG + (h2 * WW + w2) * HWSZ
                           + (2 * y1) * WW + 2 * x1;
        unsigned long long patch2[25];
#pragma unroll
        for (int r = 0; r < KK; r++)
#pragma unroll
            for (int c = 0; c < KK; c++)
                patch2[r * KK + c] = bcast2(__ldg(src + r * WW + c));

        float* dst = g_T + (((size_t)b * COUTT) * 25 + yx) * TS_W + tid;
#pragma unroll
        for (int ip = 0; ip < NPAIR; ip++) {
            unsigned long long acc = 0ull;
#pragma unroll
            for (int k = 0; k < 25; k++)
                fma2(acc, patch2[k], ws2[k * NPAIR + ip]);
            float lo, hi;
            unpack2(acc, lo, hi);
            dst[(size_t)(2 * ip)     * 25 * TS_W] = lo;   // coalesced over tid
            dst[(size_t)(2 * ip + 1) * 25 * TS_W] = hi;
        }
    }
}

// ---------------------------------------------------------------------------
// Kernel 3: second conv (dims 2,3) + fused mean path.
// out_cov[b,i,q,p] = sum_a w[i,a] * T[b,i,p,win_q(a)]
// out_mean[b,i,y,x] = sum_a w[i,a] * usum[b, win_{y,x}(a)]
// grid = B*COUT, block = 640 (tid<625 cov, then tid<25 mean)
// ---------------------------------------------------------------------------
__global__ void conv2_kernel(const float* __restrict__ w,
                             float* __restrict__ out_cov,
                             float* __restrict__ out_mean) {
    __shared__ float Ts[25 * TS_W];   // 16.9 KB
    __shared__ float ws[25];
    __shared__ float us[HWSZ];
    int tid = threadIdx.x;
    int bi  = blockIdx.x;             // b*32 + i
    int i   = bi % COUTT;
    int b   = bi / COUTT;

    const float* tsrc = g_T + (size_t)bi * 25 * TS_W;
    for (int k = tid; k < 25 * TS_W; k += blockDim.x) Ts[k] = tsrc[k];
    if (tid < 25) ws[tid] = w[i * 25 + tid];
    if (tid >= 32 && tid < 32 + HWSZ) us[tid - 32] = g_usum[b * HWSZ + (tid - 32)];
    __syncthreads();

    if (tid < 625) {
        int q = tid / 25;             // y2*5+x2
        int p = tid - q * 25;         // y1*5+x1
        int y2 = q / OWW, x2 = q - y2 * OWW;
        const float* base = Ts + p * TS_W + (2 * y2) * 13 + 2 * x2;
        float acc = 0.f;
#pragma unroll
        for (int r = 0; r < KK; r++)
#pragma unroll
            for (int c = 0; c < KK; c++)
                acc += ws[r * KK + c] * base[r * 13 + c];
        out_cov[(size_t)bi * 625 + tid] = acc;   // coalesced
    }

    if (tid < 25) {                   // mean outputs for this (b,i)
        int y = tid / OWW, x = tid - y * OWW;
        const float* base = us + (2 * y) * WW + 2 * x;
        float acc = 0.f;
#pragma unroll
        for (int r = 0; r < KK; r++)
#pragma unroll
            for (int c = 0; c < KK; c++)
                acc += ws[r * KK + c] * base[r * WW + c];
        out_mean[(size_t)bi * 25 + tid] = acc;
    }
}

// ---------------------------------------------------------------------------
extern "C" void kernel_launch(void* const* d_in, const int* in_sizes, int n_in,
                              void* d_out, int out_size) {
    const float* u = (const float*)d_in[0];   // [32,16,14,14]
    const float* C = (const float*)d_in[1];   // [32,16,14,14,14,14]
    const float* w = (const float*)d_in[2];   // [32,1,5,5]
    float* out      = (float*)d_out;
    float* out_mean = out;                               // 25600 floats
    float* out_cov  = out + BB * COUTT * OHH * OWW;      // 640000 floats

    // 1) channel reductions (C: HBM-bound; u: appended blocks)
    reduce_c_kernel<<<RED_BLOCKS + USUM_BLOCKS, 256>>>((const float4*)C, u);

    // 2) first conv (dims 4,5), FFMA2, 169 needed positions
    dim3 g1(OHH * OWW, BB);
    conv1_kernel<<<g1, 192>>>(w);

    // 3) second conv (dims 2,3) + fused mean path
    conv2_kernel<<<BB * COUTT, 640>>>(w, out_cov, out_mean);
}

// round 7
// speedup vs baseline: 4.6619x; 1.0395x over previous
#include <cuda_runtime.h>

#define BB    32
#define CINN  16
#define COUTT 32
#define HH    14
#define WW    14
#define KK    5
#define OHH   5
#define OWW   5
#define HWSZ  (HH*WW)        // 196
#define IMG   (HWSZ*HWSZ)    // 38416
#define IMG4  (IMG/4)        // 9604
#define TS_W  169            // only (h2,w2) in [0,13)^2 are used by conv2
#define NPAIR (COUTT/2)      // 16 channel pairs

#define RED_BLOCKS   ((BB * IMG4 + 255) / 256)           // 1201
#define USUM_ELEMS   (BB * HWSZ)                          // 6272
#define USUM_BLOCKS  ((USUM_ELEMS + 255) / 256)           // 25

// Scratch (global device arrays; no allocations)
__device__ float g_Csum[BB * IMG];                        // 4.9 MB (L2-resident)
__device__ float g_T[(size_t)BB * COUTT * 25 * TS_W];     // 17.3 MB (L2-resident)
__device__ float g_usum[USUM_ELEMS];                      // 25 KB

// ---- packed f32x2 helpers (Blackwell FFMA2) --------------------------------
__device__ __forceinline__ unsigned long long pack2(float lo, float hi) {
    unsigned long long r;
    asm("mov.b64 %0, {%1, %2};" : "=l"(r) : "f"(lo), "f"(hi));
    return r;
}
__device__ __forceinline__ unsigned long long bcast2(float v) {
    unsigned long long r;
    asm("mov.b64 %0, {%1, %1};" : "=l"(r) : "f"(v));
    return r;
}
__device__ __forceinline__ void fma2(unsigned long long& d,
                                     unsigned long long a,
                                     unsigned long long b) {
    asm("fma.rn.f32x2 %0, %1, %2, %0;" : "+l"(d) : "l"(a), "l"(b));
}
__device__ __forceinline__ void unpack2(unsigned long long v, float& lo, float& hi) {
    asm("mov.b64 {%0, %1}, %2;" : "=f"(lo), "=f"(hi) : "l"(v));
}

// ---------------------------------------------------------------------------
// Kernel 1: blocks [0,1201):  Csum[b,hw2,hw4] = sum_c C[b,c,...]  (78.7 MB)
//           blocks [1201,1226): usum[b,hw]    = sum_c u[b,c,hw]   (0.4 MB)
// ---------------------------------------------------------------------------
__global__ void reduce_c_kernel(const float4* __restrict__ C4,
                                const float* __restrict__ u) {
    if (blockIdx.x < RED_BLOCKS) {
        int idx = blockIdx.x * blockDim.x + threadIdx.x;
        if (idx >= BB * IMG4) return;
        int b = idx / IMG4;
        int j = idx - b * IMG4;
        const float4* p = C4 + (size_t)b * CINN * IMG4 + j;
        float ax = 0.f, ay = 0.f, az = 0.f, aw = 0.f;
#pragma unroll
        for (int c = 0; c < CINN; c++) {
            float4 v = __ldcs(p + (size_t)c * IMG4);   // streaming: evict-first
            ax += v.x; ay += v.y; az += v.z; aw += v.w;
        }
        reinterpret_cast<float4*>(g_Csum)[idx] = make_float4(ax, ay, az, aw);
    } else {
        int t = (blockIdx.x - RED_BLOCKS) * blockDim.x + threadIdx.x;
        if (t >= USUM_ELEMS) return;
        int b  = t / HWSZ;
        int hw = t - b * HWSZ;
        const float* up = u + (size_t)b * CINN * HWSZ + hw;
        float a = 0.f;
#pragma unroll
        for (int c = 0; c < CINN; c++) a += up[c * HWSZ];
        g_usum[t] = a;
    }
}

// ---------------------------------------------------------------------------
// Kernel 2: first conv (dims 4,5), all 32 channels, only 169 needed (h2,w2).
// FFMA2: channels in pairs.  T[b][i][p][j] = sum_k w[i,k]*Csum[b,j,win_p(k)]
// grid = (25, B), block = 192 (tid<169 active)
// ---------------------------------------------------------------------------
__global__ void conv1_kernel(const float* __restrict__ w) {
    __shared__ unsigned long long ws2[25 * NPAIR];   // [k][ipair]
    int tid = threadIdx.x;

    for (int t = tid; t < 25 * NPAIR; t += blockDim.x) {
        int k  = t / NPAIR;
        int ip = t - k * NPAIR;
        ws2[t] = pack2(w[(2 * ip) * 25 + k], w[(2 * ip + 1) * 25 + k]);
    }
    __syncthreads();

    int yx = blockIdx.x;              // p = y1*5+x1
    int b  = blockIdx.y;
    int y1 = yx / OWW, x1 = yx - y1 * OWW;

    if (tid < TS_W) {
        int h2 = tid / 13, w2 = tid - h2 * 13;
        const float* src = g_Csum + (size_t)b * IMG + (h2 * WW + w2) * HWSZ
                           + (2 * y1) * WW + 2 * x1;
        unsigned long long patch2[25];
#pragma unroll
        for (int r = 0; r < KK; r++)
#pragma unroll
            for (int c = 0; c < KK; c++)
                patch2[r * KK + c] = bcast2(__ldg(src + r * WW + c));

        float* dst = g_T + (((size_t)b * COUTT) * 25 + yx) * TS_W + tid;
#pragma unroll
        for (int ip = 0; ip < NPAIR; ip++) {
            unsigned long long acc = 0ull;
#pragma unroll
            for (int k = 0; k < 25; k++)
                fma2(acc, patch2[k], ws2[k * NPAIR + ip]);
            float lo, hi;
            unpack2(acc, lo, hi);
            dst[(size_t)(2 * ip)     * 25 * TS_W] = lo;   // coalesced over tid
            dst[(size_t)(2 * ip + 1) * 25 * TS_W] = hi;
        }
    }
}

// ---------------------------------------------------------------------------
// Kernel 3: second conv (dims 2,3) + fused mean path.
// out_cov[b,i,q,p] = sum_a w[i,a] * T[b,i,p,win_q(a)]
// out_mean[b,i,y,x] = sum_a w[i,a] * usum[b, win_{y,x}(a)]
// grid = B*COUT, block = 640 (tid<625 cov, then tid<25 mean)
// ---------------------------------------------------------------------------
__global__ void conv2_kernel(const float* __restrict__ w,
                             float* __restrict__ out_cov,
                             float* __restrict__ out_mean) {
    __shared__ float Ts[25 * TS_W];   // 16.9 KB
    __shared__ float ws[25];
    __shared__ float us[HWSZ];
    int tid = threadIdx.x;
    int bi  = blockIdx.x;             // b*32 + i
    int i   = bi % COUTT;
    int b   = bi / COUTT;

    const float* tsrc = g_T + (size_t)bi * 25 * TS_W;
    for (int k = tid; k < 25 * TS_W; k += blockDim.x) Ts[k] = tsrc[k];
    if (tid < 25) ws[tid] = w[i * 25 + tid];
    if (tid >= 32 && tid < 32 + HWSZ) us[tid - 32] = g_usum[b * HWSZ + (tid - 32)];
    __syncthreads();

    if (tid < 625) {
        int q = tid / 25;             // y2*5+x2
        int p = tid - q * 25;         // y1*5+x1
        int y2 = q / OWW, x2 = q - y2 * OWW;
        const float* base = Ts + p * TS_W + (2 * y2) * 13 + 2 * x2;
        float acc = 0.f;
#pragma unroll
        for (int r = 0; r < KK; r++)
#pragma unroll
            for (int c = 0; c < KK; c++)
                acc += ws[r * KK + c] * base[r * 13 + c];
        out_cov[(size_t)bi * 625 + tid] = acc;   // coalesced
    }

    if (tid < 25) {                   // mean outputs for this (b,i)
        int y = tid / OWW, x = tid - y * OWW;
        const float* base = us + (2 * y) * WW + 2 * x;
        float acc = 0.f;
#pragma unroll
        for (int r = 0; r < KK; r++)
#pragma unroll
            for (int c = 0; c < KK; c++)
                acc += ws[r * KK + c] * base[r * WW + c];
        out_mean[(size_t)bi * 25 + tid] = acc;
    }
}

// ---------------------------------------------------------------------------
extern "C" void kernel_launch(void* const* d_in, const int* in_sizes, int n_in,
                              void* d_out, int out_size) {
    const float* u = (const float*)d_in[0];   // [32,16,14,14]
    const float* C = (const float*)d_in[1];   // [32,16,14,14,14,14]
    const float* w = (const float*)d_in[2];   // [32,1,5,5]
    float* out      = (float*)d_out;
    float* out_mean = out;                               // 25600 floats
    float* out_cov  = out + BB * COUTT * OHH * OWW;      // 640000 floats

    // 1) channel reductions (C: HBM-bound; u: appended blocks)
    reduce_c_kernel<<<RED_BLOCKS + USUM_BLOCKS, 256>>>((const float4*)C, u);

    // 2) first conv (dims 4,5), FFMA2, 169 needed positions
    dim3 g1(OHH * OWW, BB);
    conv1_kernel<<<g1, 192>>>(w);

    // 3) second conv (dims 2,3) + fused mean path
    conv2_kernel<<<BB * COUTT, 640>>>(w, out_cov, out_mean);
}

// round 8
// speedup vs baseline: 4.7084x; 1.0100x over previous
#include <cuda_runtime.h>

#define BB    32
#define CINN  16
#define COUTT 32
#define HH    14
#define WW    14
#define KK    5
#define OHH   5
#define OWW   5
#define HWSZ  (HH*WW)        // 196
#define IMG   (HWSZ*HWSZ)    // 38416
#define IMG4  (IMG/4)        // 9604
#define TS_W  169            // only (h2,w2) in [0,13)^2 are used by conv2
#define NPAIR (COUTT/2)      // 16 channel pairs

#define RED_BLOCKS   ((BB * IMG4 + 255) / 256)           // 1201
#define USUM_ELEMS   (BB * HWSZ)                          // 6272
#define USUM_BLOCKS  ((USUM_ELEMS + 255) / 256)           // 25

// Scratch (global device arrays; no allocations)
__device__ float g_Csum[BB * IMG];                        // 4.9 MB (L2-resident)
__device__ float g_T[(size_t)BB * COUTT * 25 * TS_W];     // 17.3 MB (L2-resident)
__device__ float g_usum[USUM_ELEMS];                      // 25 KB

// ---- packed f32x2 helpers (Blackwell FFMA2) --------------------------------
__device__ __forceinline__ unsigned long long pack2(float lo, float hi) {
    unsigned long long r;
    asm("mov.b64 %0, {%1, %2};" : "=l"(r) : "f"(lo), "f"(hi));
    return r;
}
__device__ __forceinline__ unsigned long long bcast2(float v) {
    unsigned long long r;
    asm("mov.b64 %0, {%1, %1};" : "=l"(r) : "f"(v));
    return r;
}
__device__ __forceinline__ void fma2(unsigned long long& d,
                                     unsigned long long a,
                                     unsigned long long b) {
    asm("fma.rn.f32x2 %0, %1, %2, %0;" : "+l"(d) : "l"(a), "l"(b));
}
__device__ __forceinline__ void unpack2(unsigned long long v, float& lo, float& hi) {
    asm("mov.b64 {%0, %1}, %2;" : "=f"(lo), "=f"(hi) : "l"(v));
}

// ---------------------------------------------------------------------------
// Kernel 1: blocks [0,1201):  Csum[b,hw2,hw4] = sum_c C[b,c,...]  (78.7 MB)
//           blocks [1201,1226): usum[b,hw]    = sum_c u[b,c,hw]   (0.4 MB)
// ---------------------------------------------------------------------------
__global__ void reduce_c_kernel(const float4* __restrict__ C4,
                                const float* __restrict__ u) {
    if (blockIdx.x < RED_BLOCKS) {
        int idx = blockIdx.x * blockDim.x + threadIdx.x;
        if (idx >= BB * IMG4) return;
        int b = idx / IMG4;
        int j = idx - b * IMG4;
        const float4* p = C4 + (size_t)b * CINN * IMG4 + j;
        float ax = 0.f, ay = 0.f, az = 0.f, aw = 0.f;
#pragma unroll
        for (int c = 0; c < CINN; c++) {
            float4 v = __ldcs(p + (size_t)c * IMG4);   // streaming: evict-first
            ax += v.x; ay += v.y; az += v.z; aw += v.w;
        }
        reinterpret_cast<float4*>(g_Csum)[idx] = make_float4(ax, ay, az, aw);
    } else {
        int t = (blockIdx.x - RED_BLOCKS) * blockDim.x + threadIdx.x;
        if (t >= USUM_ELEMS) return;
        int b  = t / HWSZ;
        int hw = t - b * HWSZ;
        const float* up = u + (size_t)b * CINN * HWSZ + hw;
        float a = 0.f;
#pragma unroll
        for (int c = 0; c < CINN; c++) a += up[c * HWSZ];
        g_usum[t] = a;
    }
}

// ---------------------------------------------------------------------------
// Kernel 2: first conv (dims 4,5), all 32 channels, only 169 needed (h2,w2).
// FFMA2: channels in pairs.  T[b][i][p][j] = sum_k w[i,k]*Csum[b,j,win_p(k)]
// grid = (25, B), block = 192 (tid<169 active)
// ---------------------------------------------------------------------------
__global__ void conv1_kernel(const float* __restrict__ w) {
    __shared__ unsigned long long ws2[25 * NPAIR];   // [k][ipair]
    int tid = threadIdx.x;

    for (int t = tid; t < 25 * NPAIR; t += blockDim.x) {
        int k  = t / NPAIR;
        int ip = t - k * NPAIR;
        ws2[t] = pack2(w[(2 * ip) * 25 + k], w[(2 * ip + 1) * 25 + k]);
    }
    __syncthreads();

    int yx = blockIdx.x;              // p = y1*5+x1
    int b  = blockIdx.y;
    int y1 = yx / OWW, x1 = yx - y1 * OWW;

    if (tid < TS_W) {
        int h2 = tid / 13, w2 = tid - h2 * 13;
        const float* src = g_Csum + (size_t)b * IMG + (h2 * WW + w2) * HWSZ
                           + (2 * y1) * WW + 2 * x1;
        unsigned long long patch2[25];
#pragma unroll
        for (int r = 0; r < KK; r++)
#pragma unroll
            for (int c = 0; c < KK; c++)
                patch2[r * KK + c] = bcast2(__ldg(src + r * WW + c));

        float* dst = g_T + (((size_t)b * COUTT) * 25 + yx) * TS_W + tid;
#pragma unroll
        for (int ip = 0; ip < NPAIR; ip++) {
            unsigned long long acc = 0ull;
#pragma unroll
            for (int k = 0; k < 25; k++)
                fma2(acc, patch2[k], ws2[k * NPAIR + ip]);
            float lo, hi;
            unpack2(acc, lo, hi);
            dst[(size_t)(2 * ip)     * 25 * TS_W] = lo;   // coalesced over tid
            dst[(size_t)(2 * ip + 1) * 25 * TS_W] = hi;
        }
    }
}

// ---------------------------------------------------------------------------
// Kernel 3: second conv (dims 2,3) + fused mean path.
// out_cov[b,i,q,p] = sum_a w[i,a] * T[b,i,p,win_q(a)]
// out_mean[b,i,y,x] = sum_a w[i,a] * usum[b, win_{y,x}(a)]
// grid = B*COUT, block = 640 (tid<625 cov, then tid<25 mean)
// ---------------------------------------------------------------------------
__global__ void conv2_kernel(const float* __restrict__ w,
                             float* __restrict__ out_cov,
                             float* __restrict__ out_mean) {
    __shared__ float Ts[25 * TS_W];   // 16.9 KB
    __shared__ float ws[25];
    __shared__ float us[HWSZ];
    int tid = threadIdx.x;
    int bi  = blockIdx.x;             // b*32 + i
    int i   = bi % COUTT;
    int b   = bi / COUTT;

    const float* tsrc = g_T + (size_t)bi * 25 * TS_W;
    for (int k = tid; k < 25 * TS_W; k += blockDim.x) Ts[k] = tsrc[k];
    if (tid < 25) ws[tid] = w[i * 25 + tid];
    if (tid >= 32 && tid < 32 + HWSZ) us[tid - 32] = g_usum[b * HWSZ + (tid - 32)];
    __syncthreads();

    if (tid < 625) {
        int q = tid / 25;             // y2*5+x2
        int p = tid - q * 25;         // y1*5+x1
        int y2 = q / OWW, x2 = q - y2 * OWW;
        const float* base = Ts + p * TS_W + (2 * y2) * 13 + 2 * x2;
        float acc = 0.f;
#pragma unroll
        for (int r = 0; r < KK; r++)
#pragma unroll
            for (int c = 0; c < KK; c++)
                acc += ws[r * KK + c] * base[r * 13 + c];
        out_cov[(size_t)bi * 625 + tid] = acc;   // coalesced
    }

    if (tid < 25) {                   // mean outputs for this (b,i)
        int y = tid / OWW, x = tid - y * OWW;
        const float* base = us + (2 * y) * WW + 2 * x;
        float acc = 0.f;
#pragma unroll
        for (int r = 0; r < KK; r++)
#pragma unroll
            for (int c = 0; c < KK; c++)
                acc += ws[r * KK + c] * base[r * WW + c];
        out_mean[(size_t)bi * 25 + tid] = acc;
    }
}

// ---------------------------------------------------------------------------
extern "C" void kernel_launch(void* const* d_in, const int* in_sizes, int n_in,
                              void* d_out, int out_size) {
    const float* u = (const float*)d_in[0];   // [32,16,14,14]
    const float* C = (const float*)d_in[1];   // [32,16,14,14,14,14]
    const float* w = (const float*)d_in[2];   // [32,1,5,5]
    float* out      = (float*)d_out;
    float* out_mean = out;                               // 25600 floats
    float* out_cov  = out + BB * COUTT * OHH * OWW;      // 640000 floats

    // 1) channel reductions (C: HBM-bound; u: appended blocks)
    reduce_c_kernel<<<RED_BLOCKS + USUM_BLOCKS, 256>>>((const float4*)C, u);

    // 2) first conv (dims 4,5), FFMA2, 169 needed positions
    dim3 g1(OHH * OWW, BB);
    conv1_kernel<<<g1, 192>>>(w);

    // 3) second conv (dims 2,3) + fused mean path
    conv2_kernel<<<BB * COUTT, 640>>>(w, out_cov, out_mean);
}